// round 1
// baseline (speedup 1.0000x reference)
#include <cuda_runtime.h>
#include <cuda_bf16.h>
#include <cstdint>

// Embedding_78666620994160
// out[t, e] = (W[e, ids[t]] + b[e]) * sqrt(512)
// ids: [8*4096] int32, W: [512, 50257] f32 (row-major), b: [512] f32
// out: [8*4096, 512] f32

#define VOCAB 50257
#define EMB   512
#define N_TOKENS (8 * 4096)

__device__ __forceinline__ float ldg_f(const float* p) { return __ldg(p); }

__global__ void __launch_bounds__(512, 4)
emb_gather_kernel(const int* __restrict__ ids,
                  const float* __restrict__ W,
                  const float* __restrict__ b,
                  float* __restrict__ out)
{
    const float SCALE = 22.62741699796952f; // sqrt(512)

    // blockDim = (128, 4): x covers EMB/4 float4 lanes, y covers 4 tokens
    int token = blockIdx.x * 4 + threadIdx.y;
    if (token >= N_TOKENS) return;

    int id = __ldg(&ids[token]);

    int e4 = threadIdx.x;          // 0..127  (float4 index along EMB)
    float4 bv = __ldg(((const float4*)b) + e4);

    // Column gather: 4 independent strided loads (each its own 32B sector).
    const float* wp = W + (size_t)(e4 * 4) * VOCAB + id;
    float x0 = ldg_f(wp);
    float x1 = ldg_f(wp + (size_t)VOCAB);
    float x2 = ldg_f(wp + (size_t)2 * VOCAB);
    float x3 = ldg_f(wp + (size_t)3 * VOCAB);

    float4 r;
    r.x = (x0 + bv.x) * SCALE;
    r.y = (x1 + bv.y) * SCALE;
    r.z = (x2 + bv.z) * SCALE;
    r.w = (x3 + bv.w) * SCALE;

    // Fully coalesced 16B store
    ((float4*)out)[(size_t)token * (EMB / 4) + e4] = r;
}

extern "C" void kernel_launch(void* const* d_in, const int* in_sizes, int n_in,
                              void* d_out, int out_size)
{
    const int*   ids = (const int*)d_in[0];    // [32768] int32
    const float* W   = (const float*)d_in[1];  // [512*50257]
    const float* b   = (const float*)d_in[2];  // [512]
    float*       out = (float*)d_out;          // [32768*512]

    dim3 block(128, 4, 1);
    dim3 grid(N_TOKENS / 4, 1, 1);
    emb_gather_kernel<<<grid, block>>>(ids, W, b, out);
}